// round 8
// baseline (speedup 1.0000x reference)
#include <cuda_runtime.h>

#define B_   4
#define S_   1024
#define H_   16
#define D_   128
#define HID  2048
#define M_   (B_ * S_)

#define BM 128
#define BN 128
#define BK 32
#define NSTAGE 3

#define A_BYTES (BM * BK * 4)              // 16384
#define B_BYTES (BN * BK * 4)              // 16384
#define STAGE_BYTES (A_BYTES + B_BYTES)    // 32768
#define SMEM_BYTES (NSTAGE * STAGE_BYTES)  // 98304
#define TLD 132                            // padded transpose ld (floats)

// ---------------------------------------------------------------------------
// Scratch
// ---------------------------------------------------------------------------
__device__ float g_q[B_ * H_ * S_ * D_];       // [b][h][s][d]  (tf32-rounded)
__device__ float g_k[B_ * H_ * S_ * D_];       // [b][h][s][d]  (tf32-rounded)
__device__ float g_v[B_ * H_ * S_ * D_];       // [b][h][d][s]  (tf32-rounded)
__device__ float g_p[B_ * H_ * S_ * S_];       // e = exp(scores), tf32-rounded
__device__ float g_att[M_ * HID];              // attended (raw fp32)
__device__ float g_inv[B_ * H_ * S_];          // 1/rowsum per (b,h,q)

__device__ __forceinline__ unsigned f2tf(float f) {
    unsigned r; asm("cvt.rn.tf32.f32 %0, %1;" : "=r"(r) : "f"(f)); return r;
}
__device__ __forceinline__ float tfr(float f) { return __uint_as_float(f2tf(f)); }
__device__ __forceinline__ unsigned tfbits(unsigned bits) {
    return f2tf(__uint_as_float(bits));
}

__device__ __forceinline__ void mma8(float* c, const unsigned* a, const unsigned* b) {
    asm volatile(
        "mma.sync.aligned.m16n8k8.row.col.f32.tf32.tf32.f32 "
        "{%0,%1,%2,%3}, {%4,%5,%6,%7}, {%8,%9}, {%0,%1,%2,%3};"
        : "+f"(c[0]), "+f"(c[1]), "+f"(c[2]), "+f"(c[3])
        : "r"(a[0]), "r"(a[1]), "r"(a[2]), "r"(a[3]), "r"(b[0]), "r"(b[1]));
}
#define LDSM4(r0, r1, r2, r3, addr)                                            \
    asm volatile("ldmatrix.sync.aligned.m8n8.x4.shared.b16 {%0,%1,%2,%3}, [%4];" \
                 : "=r"(r0), "=r"(r1), "=r"(r2), "=r"(r3) : "r"(addr))

__device__ __forceinline__ unsigned swz(unsigned row, unsigned cu) {
    return row * 128u + ((cu ^ (row & 7u)) * 16u);
}

// ---------------------------------------------------------------------------
// tf32 tensor-core NT GEMM. CTA 128x128, 256 threads (8 warps, 2x4 of 64x32),
// cp.async 3-stage, ldmatrix frags, 2 CTAs/SM (16 warps/SM).
// CVT=1: inputs raw fp32; fragments tf32-rounded in registers.
// MODE 0: Q/K scatter -> [b][h][s][d], round((acc+bias[n])*rope)
// MODE 1: V -> [b][h][d][s] via smem transpose, round(acc+bias[n])
// MODE 2: C[zoff+m*ldc+n] = alpha*acc (*rsc[z*S+m]) (+bias), raw fp32
// MODE 3: C[zoff+m*ldc+n] = round(exp(alpha*acc))
// ---------------------------------------------------------------------------
template <int CVT, int MODE>
__global__ __launch_bounds__(256, 2)
void gemm_tc(const float* __restrict__ A, const float* __restrict__ Bm,
             float* __restrict__ C, const float* __restrict__ bias,
             const float* __restrict__ rope, const float* __restrict__ rsc,
             int K, long sA, long sB, long sCb, long sCh,
             float alpha, int ldc)
{
    extern __shared__ char smem[];
    const unsigned sbase = (unsigned)__cvta_generic_to_shared(smem);
    const int tid = threadIdx.x;
    const int z = blockIdx.z;
    A  += (long)z * sA;
    Bm += (long)z * sB;
    const long zoff = (long)(z >> 4) * sCb + (long)(z & 15) * sCh;

    const int m0 = blockIdx.y * BM;
    const int n0 = blockIdx.x * BN;

    const int lane = tid & 31, wid = tid >> 5;
    const int wm = wid & 1, wn = wid >> 1;          // warp grid 2 x 4, 64x32 tiles
    const int g = lane >> 2, tg = lane & 3;

    const int ksa = lane >> 4;
    unsigned arow[4], acx[4];
#pragma unroll
    for (int mf = 0; mf < 4; mf++) {
        const int r = wm * 64 + mf * 16 + (lane & 15);
        arow[mf] = r * 128u; acx[mf] = r & 7u;
    }
    const int t = lane >> 3;
    const int ksb = t & 1;
    unsigned brow[2], bcx[2];
#pragma unroll
    for (int p = 0; p < 2; p++) {
        const int r = wn * 32 + p * 16 + ((t & 2) << 2) + (lane & 7);
        brow[p] = r * 128u; bcx[p] = r & 7u;
    }

    float acc[4][4][4];
#pragma unroll
    for (int i = 0; i < 4; i++)
#pragma unroll
        for (int j = 0; j < 4; j++)
#pragma unroll
            for (int q = 0; q < 4; q++) acc[i][j][q] = 0.f;

#define ISSUE(st)                                                               \
    {                                                                           \
        const unsigned bufb = sbase + ((st) % NSTAGE) * STAGE_BYTES;            \
        const long k0 = (long)(st) * BK;                                        \
        _Pragma("unroll") for (int i = 0; i < 4; i++) {                         \
            const int u = tid + i * 256, row = u >> 3, cu = u & 7;              \
            const float* src = A + (long)(m0 + row) * K + k0 + cu * 4;          \
            asm volatile("cp.async.cg.shared.global [%0], [%1], 16;"            \
                         :: "r"(bufb + swz(row, cu)), "l"(src));                \
        }                                                                       \
        _Pragma("unroll") for (int i = 0; i < 4; i++) {                         \
            const int u = tid + i * 256, row = u >> 3, cu = u & 7;              \
            const float* src = Bm + (long)(n0 + row) * K + k0 + cu * 4;         \
            asm volatile("cp.async.cg.shared.global [%0], [%1], 16;"            \
                         :: "r"(bufb + (unsigned)A_BYTES + swz(row, cu)), "l"(src)); \
        }                                                                       \
    }

    const int nst = K / BK;

#pragma unroll
    for (int st = 0; st < NSTAGE - 1; st++) {
        if (st < nst) ISSUE(st);
        asm volatile("cp.async.commit_group;" ::: "memory");
    }

    for (int s = 0; s < nst; s++) {
        asm volatile("cp.async.wait_group 1;" ::: "memory");
        __syncthreads();

        if (s + NSTAGE - 1 < nst) ISSUE(s + NSTAGE - 1);
        asm volatile("cp.async.commit_group;" ::: "memory");

        const unsigned ab = sbase + (s % NSTAGE) * STAGE_BYTES;
        const unsigned bbuf = ab + (unsigned)A_BYTES;
#pragma unroll
        for (int kk = 0; kk < 4; kk++) {
            unsigned afr[4][4], bfr[4][2];
#pragma unroll
            for (int mf = 0; mf < 4; mf++) {
                const unsigned cu = (unsigned)(kk * 2 + ksa);
                LDSM4(afr[mf][0], afr[mf][1], afr[mf][2], afr[mf][3],
                      ab + arow[mf] + ((cu ^ acx[mf]) << 4));
            }
#pragma unroll
            for (int p = 0; p < 2; p++) {
                const unsigned cu = (unsigned)(kk * 2 + ksb);
                LDSM4(bfr[2 * p][0], bfr[2 * p][1], bfr[2 * p + 1][0], bfr[2 * p + 1][1],
                      bbuf + brow[p] + ((cu ^ bcx[p]) << 4));
            }
            if (CVT) {
#pragma unroll
                for (int mf = 0; mf < 4; mf++)
#pragma unroll
                    for (int i = 0; i < 4; i++) afr[mf][i] = tfbits(afr[mf][i]);
#pragma unroll
                for (int nf = 0; nf < 4; nf++)
#pragma unroll
                    for (int i = 0; i < 2; i++) bfr[nf][i] = tfbits(bfr[nf][i]);
            }
#pragma unroll
            for (int mf = 0; mf < 4; mf++)
#pragma unroll
                for (int nf = 0; nf < 4; nf++)
                    mma8(acc[mf][nf], afr[mf], bfr[nf]);
        }
    }

    const int hh = n0 >> 7;

    if (MODE == 1) {
        // ---- V epilogue: smem transpose -> coalesced [b][h][d][s] stores ----
        asm volatile("cp.async.wait_group 0;" ::: "memory");
        __syncthreads();
        float* smf = (float*)smem;
#pragma unroll
        for (int mf = 0; mf < 4; mf++)
#pragma unroll
            for (int half = 0; half < 2; half++) {
                const int mloc = wm * 64 + mf * 16 + g + half * 8;
#pragma unroll
                for (int nf = 0; nf < 4; nf++) {
                    const int dd = wn * 32 + nf * 8 + 2 * tg;
                    smf[dd * TLD + mloc]       = tfr(acc[mf][nf][half * 2 + 0] + bias[n0 + dd]);
                    smf[(dd + 1) * TLD + mloc] = tfr(acc[mf][nf][half * 2 + 1] + bias[n0 + dd + 1]);
                }
            }
        __syncthreads();
        const int bb = m0 >> 10, ss0 = m0 & 1023;
        const int rrow = tid >> 1, mh = tid & 1;
        float* gdst = C + (long)(bb * H_ + hh) * D_ * S_ + (long)rrow * S_ + ss0 + mh * 64;
        const float* srcr = smf + rrow * TLD + mh * 64;
#pragma unroll
        for (int j = 0; j < 16; j++)
            *(float4*)(gdst + 4 * j) = *(const float4*)(srcr + 4 * j);
        return;
    }

#pragma unroll
    for (int mf = 0; mf < 4; mf++) {
#pragma unroll
        for (int half = 0; half < 2; half++) {
            const int m = m0 + wm * 64 + mf * 16 + g + half * 8;
            if (MODE == 0) {
                const int bb = m >> 10, ss = m & 1023;
                float* base = C + (((long)(bb * H_ + hh)) * S_ + ss) * D_;
                const float* rp = rope + ss * 128;
#pragma unroll
                for (int nf = 0; nf < 4; nf++) {
                    const int dd = wn * 32 + nf * 8 + 2 * tg;
                    float2 v;
                    v.x = tfr((acc[mf][nf][half * 2 + 0] + bias[n0 + dd])     * rp[dd]);
                    v.y = tfr((acc[mf][nf][half * 2 + 1] + bias[n0 + dd + 1]) * rp[dd + 1]);
                    *(float2*)(base + dd) = v;
                }
            } else if (MODE == 3) {
                float* crow = C + zoff + (long)m * ldc + n0;
#pragma unroll
                for (int nf = 0; nf < 4; nf++) {
                    const int dd = wn * 32 + nf * 8 + 2 * tg;
                    float2 v;
                    v.x = tfr(__expf(alpha * acc[mf][nf][half * 2 + 0]));
                    v.y = tfr(__expf(alpha * acc[mf][nf][half * 2 + 1]));
                    *(float2*)(crow + dd) = v;
                }
            } else {
                float* crow = C + zoff + (long)m * ldc + n0;
                const float rs = rsc ? rsc[(long)z * S_ + m] : 1.f;
#pragma unroll
                for (int nf = 0; nf < 4; nf++) {
                    const int dd = wn * 32 + nf * 8 + 2 * tg;
                    float x = alpha * acc[mf][nf][half * 2 + 0] * rs;
                    float y = alpha * acc[mf][nf][half * 2 + 1] * rs;
                    if (bias) { x += bias[n0 + dd]; y += bias[n0 + dd + 1]; }
                    float2 v; v.x = x; v.y = y;
                    *(float2*)(crow + dd) = v;
                }
            }
        }
    }
}

// ---------------------------------------------------------------------------
// Per-row sum -> inv, plus head-mean output. One block per (b,q), 16 warps.
// P holds e=exp(scores). No writes to P.
// ---------------------------------------------------------------------------
#define SMX_SMEM (16 * 1032 * 4)
__global__ __launch_bounds__(512)
void mean_inv(const float* __restrict__ P, float* __restrict__ outm,
              float* __restrict__ invv)
{
    extern __shared__ float sm[];                   // [16][1032]
    const int bid = blockIdx.x;                     // b*1024 + q
    const int b = bid >> 10, q = bid & 1023;
    const int wid = threadIdx.x >> 5, lane = threadIdx.x & 31;

    const float* row = P + (((long)(b * H_ + wid) * S_ + q) * S_);

    float4 v[8];
    float sum = 0.f;
#pragma unroll
    for (int w = 0; w < 8; w++) {
        v[w] = *(const float4*)&row[w * 128 + lane * 4];
        sum += v[w].x + v[w].y + v[w].z + v[w].w;
    }
#pragma unroll
    for (int o = 16; o; o >>= 1) sum += __shfl_xor_sync(0xffffffffu, sum, o);

    const float inv = 1.f / sum;
    if (lane == 0) invv[(long)(b * H_ + wid) * S_ + q] = inv;

    float* accr = sm + wid * 1032;
#pragma unroll
    for (int w = 0; w < 8; w++) {
        float4 r;
        r.x = v[w].x * inv; r.y = v[w].y * inv;
        r.z = v[w].z * inv; r.w = v[w].w * inv;
        *(float4*)&accr[w * 128 + lane * 4] = r;
    }
    __syncthreads();

    for (int c = threadIdx.x; c < S_; c += 512) {
        float s = 0.f;
#pragma unroll
        for (int h = 0; h < H_; h++) s += sm[h * 1032 + c];
        outm[(long)bid * S_ + c] = s * (1.f / (float)H_);
    }
}

// ---------------------------------------------------------------------------
extern "C" void kernel_launch(void* const* d_in, const int* in_sizes, int n_in,
                              void* d_out, int out_size)
{
    const float* query = (const float*)d_in[0];
    const float* key   = (const float*)d_in[1];
    const float* value = (const float*)d_in[2];
    const float* Wq  = (const float*)d_in[4];
    const float* bq  = (const float*)d_in[5];
    const float* Wk  = (const float*)d_in[6];
    const float* bk  = (const float*)d_in[7];
    const float* Wv  = (const float*)d_in[8];
    const float* bv  = (const float*)d_in[9];
    const float* Wo  = (const float*)d_in[10];
    const float* bo  = (const float*)d_in[11];
    const float* rot = (const float*)d_in[12];

    float* out      = (float*)d_out;
    float* out_mean = (float*)d_out + (long)B_ * S_ * HID;

    float *pq, *pk, *pv, *pp, *patt, *pinv;
    cudaGetSymbolAddress((void**)&pq,   g_q);
    cudaGetSymbolAddress((void**)&pk,   g_k);
    cudaGetSymbolAddress((void**)&pv,   g_v);
    cudaGetSymbolAddress((void**)&pp,   g_p);
    cudaGetSymbolAddress((void**)&patt, g_att);
    cudaGetSymbolAddress((void**)&pinv, g_inv);

    cudaFuncSetAttribute(gemm_tc<1,0>, cudaFuncAttributeMaxDynamicSharedMemorySize, SMEM_BYTES);
    cudaFuncSetAttribute(gemm_tc<1,1>, cudaFuncAttributeMaxDynamicSharedMemorySize, SMEM_BYTES);
    cudaFuncSetAttribute(gemm_tc<0,3>, cudaFuncAttributeMaxDynamicSharedMemorySize, SMEM_BYTES);
    cudaFuncSetAttribute(gemm_tc<0,2>, cudaFuncAttributeMaxDynamicSharedMemorySize, SMEM_BYTES);
    cudaFuncSetAttribute(gemm_tc<1,2>, cudaFuncAttributeMaxDynamicSharedMemorySize, SMEM_BYTES);
    cudaFuncSetAttribute(mean_inv, cudaFuncAttributeMaxDynamicSharedMemorySize, SMX_SMEM);

    dim3 blk(256);

    // 1) projections (raw fp32 inputs; fragments tf32-rounded in-register)
    dim3 gproj(HID / BN, M_ / BM, 1);
    gemm_tc<1,0><<<gproj, blk, SMEM_BYTES>>>(query, Wq, pq, bq, rot, (const float*)0, HID,
                                             0, 0, 0, 0, 1.f, 0);
    gemm_tc<1,0><<<gproj, blk, SMEM_BYTES>>>(key,   Wk, pk, bk, rot, (const float*)0, HID,
                                             0, 0, 0, 0, 1.f, 0);
    gemm_tc<1,1><<<gproj, blk, SMEM_BYTES>>>(value, Wv, pv, bv, (const float*)0, (const float*)0, HID,
                                             0, 0, 0, 0, 1.f, 0);

    // 2) e = exp(scale * q @ k^T)   (inputs already rounded -> CVT=0)
    const float scale = 0.08838834764831845f;
    dim3 gsc(S_ / BN, S_ / BM, B_ * H_);
    gemm_tc<0,3><<<gsc, blk, SMEM_BYTES>>>(pq, pk, pp, (const float*)0, (const float*)0,
                                           (const float*)0, D_,
                                           (long)S_ * D_, (long)S_ * D_,
                                           (long)H_ * S_ * S_, (long)S_ * S_,
                                           scale, S_);

    // 3) per-row inv + head mean
    mean_inv<<<B_ * S_, 512, SMX_SMEM>>>(pp, out_mean, pinv);

    // 4) attended = inv[q] * (e @ V)
    dim3 gpv(D_ / BN, S_ / BM, B_ * H_);
    gemm_tc<0,2><<<gpv, blk, SMEM_BYTES>>>(pp, pv, patt, (const float*)0, (const float*)0, pinv, S_,
                                           (long)S_ * S_, (long)D_ * S_,
                                           (long)S_ * HID, (long)D_,
                                           1.f, HID);

    // 5) out = att @ Wo^T + bo  (raw att + raw Wo -> CVT=1)
    gemm_tc<1,2><<<gproj, blk, SMEM_BYTES>>>(patt, Wo, out, bo, (const float*)0, (const float*)0, HID,
                                             0, 0, 0, 0, 1.f, HID);

    (void)in_sizes; (void)n_in; (void)out_size;
}